// round 8
// baseline (speedup 1.0000x reference)
#include <cuda_runtime.h>
#include <cuda_bf16.h>

// Problem constants (fixed by the reference setup_inputs)
#define NB    8      // batch
#define HH    28     // input H = W
#define NC    32     // channels (== warp size == one 128B line of floats)
#define HO    14     // output H = W
#define NOUT  196    // HO*HO
#define NIN   784    // HH*HH

// Scratch: flat input spatial index of the per-(b,i,c) argmax,
// laid out [b][i][c] so a warp (lane=c) reads one coalesced line per i.
__device__ int g_sidx[NB * NOUT * NC];

// ---------------------------------------------------------------------------
// Kernel A: 2x2 max-pool argmax -> mu_out + gather index.
// One thread per (b, oy, ox, c); 50176 threads total.
// ---------------------------------------------------------------------------
__global__ void pool_idx_kernel(const float* __restrict__ mu,
                                float* __restrict__ out_mu) {
    int t = blockIdx.x * blockDim.x + threadIdx.x;
    if (t < NB * NOUT * NC) {
        int c = t & (NC - 1);
        int p = t >> 5;            // b*196 + i
        int i = p % NOUT;
        int oy = i / HO, ox = i - oy * HO;
        int iy = 2 * oy, ix = 2 * ox;
        int b = p / NOUT;

        const float* base = mu + ((b * HH + iy) * HH + ix) * NC + c;
        float v00 = base[0];
        float v01 = base[NC];
        float v10 = base[HH * NC];
        float v11 = base[HH * NC + NC];

        // first-match argmax over row-major order (0,0),(0,1),(1,0),(1,1)
        float best = v00; int k = 0;
        if (v01 > best) { best = v01; k = 1; }
        if (v10 > best) { best = v10; k = 2; }
        if (v11 > best) { best = v11; k = 3; }
        int dy = k >> 1, dx = k & 1;

        out_mu[t] = best;
        g_sidx[t] = (iy + dy) * HH + (ix + dx);   // flat input spatial index
    }
    // PDL: allow the dependent gather kernel to begin its prologue early.
    cudaTriggerProgrammaticLaunchCompletion();
}

// ---------------------------------------------------------------------------
// Kernel B: Sigma double-gather — R7 body, but forced to 6 blocks/SM
// (launch_bounds min-blocks) to raise resident warps 35 -> 48 while keeping
// the 25-deep back-to-back gather batch. In-flight gathers/SM: 875 -> ~1200.
// ---------------------------------------------------------------------------
#define JMAX 25

__global__ void __launch_bounds__(256, 6)
sigma_gather_kernel(const float* __restrict__ S, float* __restrict__ outS) {
    int b = blockIdx.x / NOUT;
    int i = blockIdx.x - b * NOUT;
    int c = threadIdx.x & 31;
    int w = threadIdx.x >> 5;  // 0..7

    // even-ish split: warps 0-3 get 25, warps 4-7 get 24 (4*25+4*24 = 196)
    int cnt  = (w < 4) ? 25 : 24;
    int jbeg = (w < 4) ? (w * 25) : (100 + (w - 4) * 24);

    float* __restrict__ o =
        outS + ((long long)(b * NOUT + i) * NOUT) * NC + c;
    const int* __restrict__ sj_base = &g_sidx[b * NOUT * NC + c];

    // Wait for pool_idx_kernel's g_sidx writes (PDL dependency).
    cudaGridDependencySynchronize();

    int my_sidx = __ldg(&g_sidx[(b * NOUT + i) * NC + c]);
    const float* __restrict__ Sp =
        S + (long long)b * (NIN * (long long)NIN * NC)
          + (long long)my_sidx * (NIN * NC) + c;

    // preload column spatial indices (L2-resident scratch); tail lanes
    // duplicate j=jbeg (harmless L2-hit dummy)
    int sj[JMAX];
#pragma unroll
    for (int t = 0; t < JMAX; t++) {
        int j = jbeg + ((t < cnt) ? t : 0);
        sj[t] = __ldg(sj_base + j * NC);
    }

    // issue all gathers back-to-back (evict-first: zero reuse)
    float v[JMAX];
#pragma unroll
    for (int t = 0; t < JMAX; t++) {
        v[t] = __ldcs(Sp + (long long)sj[t] * NC);
    }

    // coalesced streaming stores
#pragma unroll
    for (int t = 0; t < JMAX; t++) {
        if (t < cnt) __stcs(o + (jbeg + t) * NC, v[t]);
    }
}

// ---------------------------------------------------------------------------
// Launch: d_in[0] = mu_in [8,28,28,32] f32, d_in[1] = Sigma_in [8,784,784,32] f32
// d_out = mu_out (50176 floats) followed by Sigma_out (9834496 floats).
// ---------------------------------------------------------------------------
extern "C" void kernel_launch(void* const* d_in, const int* in_sizes, int n_in,
                              void* d_out, int out_size) {
    const float* mu    = (const float*)d_in[0];
    const float* Sigma = (const float*)d_in[1];
    float* out   = (float*)d_out;
    float* outMu = out;
    float* outS  = out + NB * NOUT * NC;   // 50176

    pool_idx_kernel<<<(NB * NOUT * NC + 255) / 256, 256>>>(mu, outMu);

    // Programmatic dependent launch: B's prologue overlaps A + launch latency.
    cudaLaunchAttribute attrs[1];
    attrs[0].id = cudaLaunchAttributeProgrammaticStreamSerialization;
    attrs[0].val.programmaticStreamSerializationAllowed = 1;
    cudaLaunchConfig_t cfg = {};
    cfg.gridDim  = dim3(NB * NOUT, 1, 1);
    cfg.blockDim = dim3(256, 1, 1);
    cfg.dynamicSmemBytes = 0;
    cfg.stream = 0;
    cfg.attrs = attrs;
    cfg.numAttrs = 1;
    cudaLaunchKernelEx(&cfg, sigma_gather_kernel, Sigma, outS);
}

// round 9
// speedup vs baseline: 1.0447x; 1.0447x over previous
#include <cuda_runtime.h>
#include <cuda_bf16.h>

// Problem constants (fixed by the reference setup_inputs)
#define NB    8      // batch
#define HH    28     // input H = W
#define NC    32     // channels (== warp size == one 128B line of floats)
#define HO    14     // output H = W
#define NOUT  196    // HO*HO
#define NIN   784    // HH*HH

// Scratch: flat input spatial index of the per-(b,i,c) argmax,
// laid out [b][i][c] so a warp (lane=c) reads one coalesced line per i.
__device__ int g_sidx[NB * NOUT * NC];

// ---------------------------------------------------------------------------
// Kernel A: 2x2 max-pool argmax -> mu_out + gather index.
// One thread per (b, oy, ox, c); 50176 threads total (98 blocks x 512).
// ---------------------------------------------------------------------------
__global__ void pool_idx_kernel(const float* __restrict__ mu,
                                float* __restrict__ out_mu) {
    int t = blockIdx.x * blockDim.x + threadIdx.x;
    if (t < NB * NOUT * NC) {
        int c = t & (NC - 1);
        int p = t >> 5;            // b*196 + i
        int i = p % NOUT;
        int oy = i / HO, ox = i - oy * HO;
        int iy = 2 * oy, ix = 2 * ox;
        int b = p / NOUT;

        const float* base = mu + ((b * HH + iy) * HH + ix) * NC + c;
        float v00 = base[0];
        float v01 = base[NC];
        float v10 = base[HH * NC];
        float v11 = base[HH * NC + NC];

        // first-match argmax over row-major order (0,0),(0,1),(1,0),(1,1)
        float best = v00; int k = 0;
        if (v01 > best) { best = v01; k = 1; }
        if (v10 > best) { best = v10; k = 2; }
        if (v11 > best) { best = v11; k = 3; }
        int dy = k >> 1, dx = k & 1;

        out_mu[t] = best;
        g_sidx[t] = (iy + dy) * HH + (ix + dx);   // flat input spatial index
    }
    // PDL: allow the dependent gather kernel to begin its prologue early.
    cudaTriggerProgrammaticLaunchCompletion();
}

// ---------------------------------------------------------------------------
// Kernel B: Sigma double-gather — best-measured body (R2/R7) + PDL.
// grid.x = NB*NOUT blocks; block = 256 threads (8 warps). Block owns (b, i);
// lane = channel c. Warps 0-3 own 25 j's, warps 4-7 own 24. 24 column
// indices preloaded + gathers issued back-to-back (warps 0-3 do a 25th
// unconditionally-real one — no dummy duplicate fetch), then coalesced
// 128B streaming stores. DRAM-activation-bound at ~6.44 TB/s.
// ---------------------------------------------------------------------------
#define JBASE 24

__global__ void __launch_bounds__(256)
sigma_gather_kernel(const float* __restrict__ S, float* __restrict__ outS) {
    int b = blockIdx.x / NOUT;
    int i = blockIdx.x - b * NOUT;
    int c = threadIdx.x & 31;
    int w = threadIdx.x >> 5;  // 0..7

    // warps 0-3: 25 j's, warps 4-7: 24 (4*25 + 4*24 = 196)
    bool extra = (w < 4);
    int jbeg = extra ? (w * 25) : (100 + (w - 4) * 24);

    float* __restrict__ o =
        outS + ((long long)(b * NOUT + i) * NOUT) * NC + c;
    const int* __restrict__ sj_base = &g_sidx[b * NOUT * NC + c];

    // Wait for pool_idx_kernel's g_sidx writes (PDL dependency).
    cudaGridDependencySynchronize();

    int my_sidx = __ldg(&g_sidx[(b * NOUT + i) * NC + c]);
    const float* __restrict__ Sp =
        S + (long long)b * (NIN * (long long)NIN * NC)
          + (long long)my_sidx * (NIN * NC) + c;

    // preload column spatial indices (L2-resident scratch)
    int sj[JBASE];
#pragma unroll
    for (int t = 0; t < JBASE; t++)
        sj[t] = __ldg(sj_base + (jbeg + t) * NC);
    int sj24 = 0;
    if (extra) sj24 = __ldg(sj_base + (jbeg + JBASE) * NC);

    // issue all gathers back-to-back (evict-first: zero reuse)
    float v[JBASE];
#pragma unroll
    for (int t = 0; t < JBASE; t++)
        v[t] = __ldcs(Sp + (long long)sj[t] * NC);
    float v24 = 0.0f;
    if (extra) v24 = __ldcs(Sp + (long long)sj24 * NC);

    // coalesced streaming stores
#pragma unroll
    for (int t = 0; t < JBASE; t++)
        __stcs(o + (jbeg + t) * NC, v[t]);
    if (extra) __stcs(o + (jbeg + JBASE) * NC, v24);
}

// ---------------------------------------------------------------------------
// Launch: d_in[0] = mu_in [8,28,28,32] f32, d_in[1] = Sigma_in [8,784,784,32] f32
// d_out = mu_out (50176 floats) followed by Sigma_out (9834496 floats).
// ---------------------------------------------------------------------------
extern "C" void kernel_launch(void* const* d_in, const int* in_sizes, int n_in,
                              void* d_out, int out_size) {
    const float* mu    = (const float*)d_in[0];
    const float* Sigma = (const float*)d_in[1];
    float* out   = (float*)d_out;
    float* outMu = out;
    float* outS  = out + NB * NOUT * NC;   // 50176

    pool_idx_kernel<<<(NB * NOUT * NC + 511) / 512, 512>>>(mu, outMu);

    // Programmatic dependent launch: B's prologue overlaps A + launch latency.
    cudaLaunchAttribute attrs[1];
    attrs[0].id = cudaLaunchAttributeProgrammaticStreamSerialization;
    attrs[0].val.programmaticStreamSerializationAllowed = 1;
    cudaLaunchConfig_t cfg = {};
    cfg.gridDim  = dim3(NB * NOUT, 1, 1);
    cfg.blockDim = dim3(256, 1, 1);
    cfg.dynamicSmemBytes = 0;
    cfg.stream = 0;
    cfg.attrs = attrs;
    cfg.numAttrs = 1;
    cudaLaunchKernelEx(&cfg, sigma_gather_kernel, Sigma, outS);
}

// round 10
// speedup vs baseline: 1.5325x; 1.4669x over previous
#include <cuda_runtime.h>
#include <cuda_bf16.h>

// Problem constants (fixed by the reference setup_inputs)
#define NB    8      // batch
#define HH    28     // input H = W
#define NC    32     // channels (== warp size == one 128B line of floats)
#define HO    14     // output H = W
#define NOUT  196    // HO*HO
#define NIN   784    // HH*HH

// Scratch: flat input spatial index of the per-(b,i,c) argmax,
// laid out [b][i][c] so a warp (lane=c) reads one coalesced line per i.
__device__ int g_sidx[NB * NOUT * NC];

// ---------------------------------------------------------------------------
// Kernel A: 2x2 max-pool argmax -> mu_out + gather index.
// One thread per (b, oy, ox, c); 50176 threads total (98 blocks x 512).
// ---------------------------------------------------------------------------
__global__ void pool_idx_kernel(const float* __restrict__ mu,
                                float* __restrict__ out_mu) {
    int t = blockIdx.x * blockDim.x + threadIdx.x;
    if (t < NB * NOUT * NC) {
        int c = t & (NC - 1);
        int p = t >> 5;            // b*196 + i
        int i = p % NOUT;
        int oy = i / HO, ox = i - oy * HO;
        int iy = 2 * oy, ix = 2 * ox;
        int b = p / NOUT;

        const float* base = mu + ((b * HH + iy) * HH + ix) * NC + c;
        float v00 = base[0];
        float v01 = base[NC];
        float v10 = base[HH * NC];
        float v11 = base[HH * NC + NC];

        // first-match argmax over row-major order (0,0),(0,1),(1,0),(1,1)
        float best = v00; int k = 0;
        if (v01 > best) { best = v01; k = 1; }
        if (v10 > best) { best = v10; k = 2; }
        if (v11 > best) { best = v11; k = 3; }
        int dy = k >> 1, dx = k & 1;

        out_mu[t] = best;
        g_sidx[t] = (iy + dy) * HH + (ix + dx);   // flat input spatial index
    }
    // PDL: allow the dependent gather kernel to begin its prologue early.
    cudaTriggerProgrammaticLaunchCompletion();
}

// ---------------------------------------------------------------------------
// Kernel B: Sigma double-gather — best-measured body (R9) + PDL.
// grid.x = NB*NOUT blocks; block = 256 threads (8 warps). Block owns (b, i);
// lane = channel c. Warps 0-3 own 25 j's, warps 4-7 own 24. Column indices
// preloaded (L2-resident scratch), all gathers issued back-to-back
// (evict-first; zero reuse), then coalesced 128B streaming stores.
// ---------------------------------------------------------------------------
#define JBASE 24

__global__ void __launch_bounds__(256)
sigma_gather_kernel(const float* __restrict__ S, float* __restrict__ outS) {
    int b = blockIdx.x / NOUT;
    int i = blockIdx.x - b * NOUT;
    int c = threadIdx.x & 31;
    int w = threadIdx.x >> 5;  // 0..7

    // warps 0-3: 25 j's, warps 4-7: 24 (4*25 + 4*24 = 196)
    bool extra = (w < 4);
    int jbeg = extra ? (w * 25) : (100 + (w - 4) * 24);

    float* __restrict__ o =
        outS + ((long long)(b * NOUT + i) * NOUT) * NC + c;
    const int* __restrict__ sj_base = &g_sidx[b * NOUT * NC + c];

    // Wait for pool_idx_kernel's g_sidx writes (PDL dependency).
    cudaGridDependencySynchronize();

    int my_sidx = __ldg(&g_sidx[(b * NOUT + i) * NC + c]);
    const float* __restrict__ Sp =
        S + (long long)b * (NIN * (long long)NIN * NC)
          + (long long)my_sidx * (NIN * NC) + c;

    // preload column spatial indices (L2-resident scratch)
    int sj[JBASE];
#pragma unroll
    for (int t = 0; t < JBASE; t++)
        sj[t] = __ldg(sj_base + (jbeg + t) * NC);
    int sj24 = 0;
    if (extra) sj24 = __ldg(sj_base + (jbeg + JBASE) * NC);

    // issue all gathers back-to-back (evict-first: zero reuse)
    float v[JBASE];
#pragma unroll
    for (int t = 0; t < JBASE; t++)
        v[t] = __ldcs(Sp + (long long)sj[t] * NC);
    float v24 = 0.0f;
    if (extra) v24 = __ldcs(Sp + (long long)sj24 * NC);

    // coalesced streaming stores
#pragma unroll
    for (int t = 0; t < JBASE; t++)
        __stcs(o + (jbeg + t) * NC, v[t]);
    if (extra) __stcs(o + (jbeg + JBASE) * NC, v24);
}

// ---------------------------------------------------------------------------
// Launch: d_in[0] = mu_in [8,28,28,32] f32, d_in[1] = Sigma_in [8,784,784,32] f32
// d_out = mu_out (50176 floats) followed by Sigma_out (9834496 floats).
// ---------------------------------------------------------------------------
extern "C" void kernel_launch(void* const* d_in, const int* in_sizes, int n_in,
                              void* d_out, int out_size) {
    const float* mu    = (const float*)d_in[0];
    const float* Sigma = (const float*)d_in[1];
    float* out   = (float*)d_out;
    float* outMu = out;
    float* outS  = out + NB * NOUT * NC;   // 50176

    // Cap L2->DRAM fetch granularity at 32B: the gather touches ~26 distinct
    // 32B sectors per (i,j) but DRAM currently fetches ~13.5 full 128B lines
    // (measured). Device-persistent setting; establish it on the non-captured
    // correctness call, skip during graph capture (no captured side effects).
    cudaStreamCaptureStatus st = cudaStreamCaptureStatusNone;
    cudaStreamIsCapturing((cudaStream_t)0, &st);
    if (st == cudaStreamCaptureStatusNone) {
        (void)cudaDeviceSetLimit(cudaLimitMaxL2FetchGranularity, 32);
    }

    pool_idx_kernel<<<(NB * NOUT * NC + 511) / 512, 512>>>(mu, outMu);

    // Programmatic dependent launch: B's prologue overlaps A + launch latency.
    cudaLaunchAttribute attrs[1];
    attrs[0].id = cudaLaunchAttributeProgrammaticStreamSerialization;
    attrs[0].val.programmaticStreamSerializationAllowed = 1;
    cudaLaunchConfig_t cfg = {};
    cfg.gridDim  = dim3(NB * NOUT, 1, 1);
    cfg.blockDim = dim3(256, 1, 1);
    cfg.dynamicSmemBytes = 0;
    cfg.stream = 0;
    cfg.attrs = attrs;
    cfg.numAttrs = 1;
    cudaLaunchKernelEx(&cfg, sigma_gather_kernel, Sigma, outS);
}